// round 6
// baseline (speedup 1.0000x reference)
#include <cuda_runtime.h>
#include <cuda_bf16.h>
#include <math.h>
#include <stdint.h>

// Problem constants
#define S_TOK 4096
#define DIM   1024
#define NEXP  8
#define HID   4096
#define NSCORES (NEXP * S_TOK)

// ---------------- device scratch ----------------
__device__ float g_scores[NSCORES];
__device__ float g_thresh;
__device__ int   g_cnt[NEXP];
__device__ int   g_rows[NEXP * S_TOK];
__device__ float g_w[NEXP * S_TOK];
__device__ int   g_pos[NSCORES];
__device__ float g_hidden[(size_t)NEXP * S_TOK * HID];
__device__ float g_y[(size_t)NEXP * S_TOK * DIM];

__global__ void zero_cnt_kernel() {
    if (threadIdx.x < NEXP) g_cnt[threadIdx.x] = 0;
}

// ---------------- router (exact fp32) ----------------
__global__ void router_kernel(const float* __restrict__ x,
                              const float* __restrict__ gw,
                              const float* __restrict__ eb) {
    int s = blockIdx.x;
    int warp = threadIdx.x >> 5, lane = threadIdx.x & 31;
    const float* xs = x + (size_t)s * DIM;
    const float* g  = gw + (size_t)warp * DIM;
    float acc = 0.f;
    for (int i = lane; i < DIM; i += 32) acc += xs[i] * g[i];
    #pragma unroll
    for (int o = 16; o; o >>= 1) acc += __shfl_xor_sync(0xFFFFFFFFu, acc, o);
    __shared__ float l[NEXP];
    if (lane == 0) l[warp] = acc + eb[warp];
    __syncthreads();
    if (threadIdx.x < NEXP) {
        float m = l[0];
        #pragma unroll
        for (int e = 1; e < NEXP; e++) m = fmaxf(m, l[e]);
        float sum = 0.f;
        #pragma unroll
        for (int e = 0; e < NEXP; e++) sum += expf(l[e] - m);
        g_scores[threadIdx.x * S_TOK + s] = expf(l[threadIdx.x] - m) / sum;
    }
}

// ---------------- exact global top-k threshold (radix select) ----------------
__global__ void topk_kernel(const int* __restrict__ cap) {
    __shared__ int hist[256];
    __shared__ unsigned sh_prefix;
    __shared__ int sh_k;
    int k = S_TOK * cap[0];
    if (k < 1) k = 1;
    if (k > NSCORES) k = NSCORES;
    unsigned prefix = 0, mask = 0;
    int kk = k;
    for (int shift = 24; shift >= 0; shift -= 8) {
        for (int i = threadIdx.x; i < 256; i += blockDim.x) hist[i] = 0;
        __syncthreads();
        for (int i = threadIdx.x; i < NSCORES; i += blockDim.x) {
            unsigned u = __float_as_uint(g_scores[i]);
            if ((u & mask) == prefix) atomicAdd(&hist[(u >> shift) & 255], 1);
        }
        __syncthreads();
        if (threadIdx.x == 0) {
            int rem = kk, b = 255;
            for (; b >= 0; --b) {
                if (rem <= hist[b]) break;
                rem -= hist[b];
            }
            if (b < 0) b = 0;
            sh_prefix = prefix | ((unsigned)b << shift);
            sh_k = rem;
        }
        __syncthreads();
        prefix = sh_prefix;
        kk = sh_k;
        mask |= (0xFFu << shift);
        __syncthreads();
    }
    if (threadIdx.x == 0) g_thresh = __uint_as_float(prefix);
}

__global__ void build_kernel() {
    int i = blockIdx.x * blockDim.x + threadIdx.x;
    if (i >= NSCORES) return;
    float sc = g_scores[i];
    int e = i >> 12;
    int p = -1;
    if (sc >= g_thresh) {
        int r = atomicAdd(&g_cnt[e], 1);
        g_rows[e * S_TOK + r] = i & (S_TOK - 1);
        g_w[e * S_TOK + r]    = sc;
        p = r;
    }
    g_pos[i] = p;
}

// ---------------- tf32 tensor-core GEMM (pre-cvt smem, paired A loads) ------
#define BM 128
#define BN 128
#define BK 16
#define ASTRW 24      // As row stride in 32-bit words (pair-interleaved k)
#define BSTR 136      // Bs row stride in words

__device__ __forceinline__ unsigned f2tf(float f) {
    unsigned u;
    asm("cvt.rna.tf32.f32 %0, %1;" : "=r"(u) : "f"(f));
    return u;
}
__device__ __forceinline__ void mma_tf32(float* c, const unsigned* a, const unsigned* b) {
    asm volatile("mma.sync.aligned.m16n8k8.row.col.f32.tf32.tf32.f32 "
        "{%0,%1,%2,%3}, {%4,%5,%6,%7}, {%8,%9}, {%0,%1,%2,%3};"
        : "+f"(c[0]), "+f"(c[1]), "+f"(c[2]), "+f"(c[3])
        : "r"(a[0]), "r"(a[1]), "r"(a[2]), "r"(a[3]), "r"(b[0]), "r"(b[1]));
}

// store one 8-k group of A (floats v[0..7] = k..k+7) pair-interleaved + tf32
__device__ __forceinline__ void stage_A_group(unsigned* dst, const float* v) {
    #pragma unroll
    for (int j = 0; j < 4; j++) {
        uint2 p;
        p.x = f2tf(v[j]);       // original k = j
        p.y = f2tf(v[j + 4]);   // original k = j+4
        *(uint2*)(dst + 2 * j) = p;
    }
}

__device__ __forceinline__ void compute_bk16(const unsigned* As, const unsigned* Bs,
                                             int wm, int wn, int gid, int tig,
                                             float acc[4][4][4]) {
    #pragma unroll
    for (int ks = 0; ks < 2; ks++) {
        unsigned af[4][4], bf[4][2];
        #pragma unroll
        for (int mt = 0; mt < 4; mt++) {
            int r = wm + mt * 16 + gid;
            uint2 u02 = *(const uint2*)(As + (size_t)r * ASTRW + ks * 8 + 2 * tig);
            uint2 u13 = *(const uint2*)(As + (size_t)(r + 8) * ASTRW + ks * 8 + 2 * tig);
            af[mt][0] = u02.x;  // (gid,   k=tig)
            af[mt][1] = u13.x;  // (gid+8, k=tig)
            af[mt][2] = u02.y;  // (gid,   k=tig+4)
            af[mt][3] = u13.y;  // (gid+8, k=tig+4)
        }
        #pragma unroll
        for (int nt = 0; nt < 4; nt++) {
            const unsigned* b0 = Bs + (size_t)(ks * 8 + tig) * BSTR + wn + nt * 8 + gid;
            bf[nt][0] = b0[0];
            bf[nt][1] = b0[4 * BSTR];
        }
        #pragma unroll
        for (int mt = 0; mt < 4; mt++)
            #pragma unroll
            for (int nt = 0; nt < 4; nt++)
                mma_tf32(acc[mt][nt], af[mt], bf[nt]);
    }
}

// GEMM1: g_hidden[e][r][h] = gelu( x[tok[r]] @ w1[e] + b1[e] ),  K=DIM
__global__ __launch_bounds__(256, 2)
void gemm1_kernel(const float* __restrict__ x,
                  const float* __restrict__ w1,
                  const float* __restrict__ b1) {
    int e = blockIdx.z;
    int n = g_cnt[e];
    int row0 = blockIdx.y * BM;
    if (row0 >= n) return;
    int col0 = blockIdx.x * BN;
    const float* Bg = w1 + (size_t)e * DIM * HID;
    const int ldb = HID;
    const int K = DIM;

    __shared__ __align__(16) unsigned As[BM * ASTRW];
    __shared__ __align__(16) unsigned Bs[BK * BSTR];
    __shared__ int toks[BM];

    int tid = threadIdx.x;
    if (tid < BM) {
        int mg = row0 + tid;
        if (mg >= n) mg = n - 1;
        toks[tid] = g_rows[e * S_TOK + mg];
    }
    __syncthreads();

    int lane = tid & 31, warp = tid >> 5;
    int gid = lane >> 2, tig = lane & 3;
    int wm = (warp & 1) * 64, wn = (warp >> 1) * 32;

    float acc[4][4][4];
    #pragma unroll
    for (int mt = 0; mt < 4; mt++)
        #pragma unroll
        for (int nt = 0; nt < 4; nt++)
            #pragma unroll
            for (int i = 0; i < 4; i++) acc[mt][nt][i] = 0.f;

    // staging: A thread -> row aR, 8-k group grp; B thread -> 2 float4 rows
    int aR = tid >> 1, grp = tid & 1;
    const float* aSrc = x + (size_t)toks[aR] * DIM + grp * 8;
    unsigned* aDst = As + (size_t)aR * ASTRW + grp * 8;
    int bk0 = tid >> 5, bn0 = lane * 4;   // two rows: bk0, bk0+8
    const float* bSrc0 = Bg + (size_t)bk0 * ldb + col0 + bn0;
    const float* bSrc1 = Bg + (size_t)(bk0 + 8) * ldb + col0 + bn0;
    unsigned* bDst0 = Bs + (size_t)bk0 * BSTR + bn0;
    unsigned* bDst1 = Bs + (size_t)(bk0 + 8) * BSTR + bn0;

    float ra[8];
    float4 rb0, rb1;
    *(float4*)&ra[0] = *(const float4*)aSrc;
    *(float4*)&ra[4] = *(const float4*)(aSrc + 4);
    rb0 = *(const float4*)bSrc0;
    rb1 = *(const float4*)bSrc1;

    for (int k0 = 0;;) {
        stage_A_group(aDst, ra);
        uint4 c0, c1;
        c0.x = f2tf(rb0.x); c0.y = f2tf(rb0.y); c0.z = f2tf(rb0.z); c0.w = f2tf(rb0.w);
        c1.x = f2tf(rb1.x); c1.y = f2tf(rb1.y); c1.z = f2tf(rb1.z); c1.w = f2tf(rb1.w);
        *(uint4*)bDst0 = c0;
        *(uint4*)bDst1 = c1;
        __syncthreads();

        k0 += BK;
        bool more = (k0 < K);
        if (more) {
            *(float4*)&ra[0] = *(const float4*)(aSrc + k0);
            *(float4*)&ra[4] = *(const float4*)(aSrc + k0 + 4);
            rb0 = *(const float4*)(bSrc0 + (size_t)k0 * ldb);
            rb1 = *(const float4*)(bSrc1 + (size_t)k0 * ldb);
        }
        compute_bk16(As, Bs, wm, wn, gid, tig, acc);
        if (!more) break;
        __syncthreads();
    }

    const float* b1e = b1 + (size_t)e * HID;
    float* Hb = g_hidden + (size_t)e * S_TOK * HID;
    #pragma unroll
    for (int mt = 0; mt < 4; mt++) {
        #pragma unroll
        for (int half = 0; half < 2; half++) {
            int r = row0 + wm + mt * 16 + gid + half * 8;
            if (r >= n) continue;
            #pragma unroll
            for (int nt = 0; nt < 4; nt++) {
                int c = col0 + wn + nt * 8 + 2 * tig;
                float v0 = acc[mt][nt][half * 2 + 0] + b1e[c];
                float v1 = acc[mt][nt][half * 2 + 1] + b1e[c + 1];
                float t0 = tanhf(0.7978845608028654f * (v0 + 0.044715f * v0 * v0 * v0));
                float t1 = tanhf(0.7978845608028654f * (v1 + 0.044715f * v1 * v1 * v1));
                float2 o;
                o.x = 0.5f * v0 * (1.0f + t0);
                o.y = 0.5f * v1 * (1.0f + t1);
                *(float2*)&Hb[(size_t)r * HID + c] = o;
            }
        }
    }
}

// GEMM2: g_y[e][r][d] = g_w[r] * ( g_hidden[e][r] @ w2[e] + b2[e] ),  K=HID
__global__ __launch_bounds__(256, 2)
void gemm2_kernel(const float* __restrict__ w2,
                  const float* __restrict__ b2) {
    int e = blockIdx.z;
    int n = g_cnt[e];
    int row0 = blockIdx.y * BM;
    if (row0 >= n) return;
    int col0 = blockIdx.x * BN;
    const float* Ag = g_hidden + (size_t)e * S_TOK * HID;
    const float* Bg = w2 + (size_t)e * HID * DIM;
    const int ldb = DIM;
    const int K = HID;

    __shared__ __align__(16) unsigned As[BM * ASTRW];
    __shared__ __align__(16) unsigned Bs[BK * BSTR];

    int tid = threadIdx.x;
    int lane = tid & 31, warp = tid >> 5;
    int gid = lane >> 2, tig = lane & 3;
    int wm = (warp & 1) * 64, wn = (warp >> 1) * 32;

    float acc[4][4][4];
    #pragma unroll
    for (int mt = 0; mt < 4; mt++)
        #pragma unroll
        for (int nt = 0; nt < 4; nt++)
            #pragma unroll
            for (int i = 0; i < 4; i++) acc[mt][nt][i] = 0.f;

    int aR = tid >> 1, grp = tid & 1;
    int mg = row0 + aR; if (mg >= n) mg = n - 1;
    const float* aSrc = Ag + (size_t)mg * HID + grp * 8;
    unsigned* aDst = As + (size_t)aR * ASTRW + grp * 8;
    int bk0 = tid >> 5, bn0 = lane * 4;
    const float* bSrc0 = Bg + (size_t)bk0 * ldb + col0 + bn0;
    const float* bSrc1 = Bg + (size_t)(bk0 + 8) * ldb + col0 + bn0;
    unsigned* bDst0 = Bs + (size_t)bk0 * BSTR + bn0;
    unsigned* bDst1 = Bs + (size_t)(bk0 + 8) * BSTR + bn0;

    float ra[8];
    float4 rb0, rb1;
    *(float4*)&ra[0] = *(const float4*)aSrc;
    *(float4*)&ra[4] = *(const float4*)(aSrc + 4);
    rb0 = *(const float4*)bSrc0;
    rb1 = *(const float4*)bSrc1;

    for (int k0 = 0;;) {
        stage_A_group(aDst, ra);
        uint4 c0, c1;
        c0.x = f2tf(rb0.x); c0.y = f2tf(rb0.y); c0.z = f2tf(rb0.z); c0.w = f2tf(rb0.w);
        c1.x = f2tf(rb1.x); c1.y = f2tf(rb1.y); c1.z = f2tf(rb1.z); c1.w = f2tf(rb1.w);
        *(uint4*)bDst0 = c0;
        *(uint4*)bDst1 = c1;
        __syncthreads();

        k0 += BK;
        bool more = (k0 < K);
        if (more) {
            *(float4*)&ra[0] = *(const float4*)(aSrc + k0);
            *(float4*)&ra[4] = *(const float4*)(aSrc + k0 + 4);
            rb0 = *(const float4*)(bSrc0 + (size_t)k0 * ldb);
            rb1 = *(const float4*)(bSrc1 + (size_t)k0 * ldb);
        }
        compute_bk16(As, Bs, wm, wn, gid, tig, acc);
        if (!more) break;
        __syncthreads();
    }

    const float* b2e = b2 + (size_t)e * DIM;
    #pragma unroll
    for (int mt = 0; mt < 4; mt++) {
        #pragma unroll
        for (int half = 0; half < 2; half++) {
            int r = row0 + wm + mt * 16 + gid + half * 8;
            if (r >= n) continue;
            float wg = g_w[e * S_TOK + r];
            #pragma unroll
            for (int nt = 0; nt < 4; nt++) {
                int c = col0 + wn + nt * 8 + 2 * tig;
                float2 o;
                o.x = wg * (acc[mt][nt][half * 2 + 0] + b2e[c]);
                o.y = wg * (acc[mt][nt][half * 2 + 1] + b2e[c + 1]);
                *(float2*)&g_y[((size_t)e * S_TOK + r) * DIM + c] = o;
            }
        }
    }
}

// ---------------- deterministic combine ----------------
__global__ void combine_kernel(float* __restrict__ out) {
    int s = blockIdx.y;
    int d = blockIdx.x * blockDim.x + threadIdx.x;
    float acc = 0.f;
    #pragma unroll
    for (int e = 0; e < NEXP; e++) {
        int p = g_pos[e * S_TOK + s];
        if (p >= 0) acc += g_y[((size_t)(e * S_TOK + p)) * DIM + d];
    }
    out[(size_t)s * DIM + d] = acc;
}

// ---------------- launch ----------------
extern "C" void kernel_launch(void* const* d_in, const int* in_sizes, int n_in,
                              void* d_out, int out_size) {
    const float* x  = (const float*)d_in[0];
    const float* gw = (const float*)d_in[1];
    const float* eb = (const float*)d_in[2];
    const float* w1 = (const float*)d_in[3];
    const float* b1 = (const float*)d_in[4];
    const float* w2 = (const float*)d_in[5];
    const float* b2 = (const float*)d_in[6];
    const int*  cap = (const int*)d_in[7];
    float* out = (float*)d_out;

    zero_cnt_kernel<<<1, 32>>>();
    router_kernel<<<S_TOK, 256>>>(x, gw, eb);
    topk_kernel<<<1, 256>>>(cap);
    build_kernel<<<NSCORES / 256, 256>>>();
    gemm1_kernel<<<dim3(HID / BN, S_TOK / BM, NEXP), 256>>>(x, w1, b1);
    gemm2_kernel<<<dim3(DIM / BN, S_TOK / BM, NEXP), 256>>>(w2, b2);
    combine_kernel<<<dim3(DIM / 256, S_TOK), 256>>>(out);
}

// round 7
// speedup vs baseline: 1.0003x; 1.0003x over previous
#include <cuda_runtime.h>
#include <cuda_bf16.h>
#include <math.h>
#include <stdint.h>

// Problem constants
#define S_TOK 4096
#define DIM   1024
#define NEXP  8
#define HID   4096
#define NSCORES (NEXP * S_TOK)

// ---------------- device scratch ----------------
__device__ float g_scores[NSCORES];
__device__ float g_thresh;
__device__ int   g_cnt[NEXP];
__device__ int   g_rows[NEXP * S_TOK];
__device__ float g_w[NEXP * S_TOK];
__device__ int   g_pos[NSCORES];
__device__ float g_hidden[(size_t)NEXP * S_TOK * HID];
__device__ float g_y[(size_t)NEXP * S_TOK * DIM];

__global__ void zero_cnt_kernel() {
    if (threadIdx.x < NEXP) g_cnt[threadIdx.x] = 0;
}

// ---------------- router (exact fp32) ----------------
__global__ void router_kernel(const float* __restrict__ x,
                              const float* __restrict__ gw,
                              const float* __restrict__ eb) {
    int s = blockIdx.x;
    int warp = threadIdx.x >> 5, lane = threadIdx.x & 31;
    const float* xs = x + (size_t)s * DIM;
    const float* g  = gw + (size_t)warp * DIM;
    float acc = 0.f;
    for (int i = lane; i < DIM; i += 32) acc += xs[i] * g[i];
    #pragma unroll
    for (int o = 16; o; o >>= 1) acc += __shfl_xor_sync(0xFFFFFFFFu, acc, o);
    __shared__ float l[NEXP];
    if (lane == 0) l[warp] = acc + eb[warp];
    __syncthreads();
    if (threadIdx.x < NEXP) {
        float m = l[0];
        #pragma unroll
        for (int e = 1; e < NEXP; e++) m = fmaxf(m, l[e]);
        float sum = 0.f;
        #pragma unroll
        for (int e = 0; e < NEXP; e++) sum += expf(l[e] - m);
        g_scores[threadIdx.x * S_TOK + s] = expf(l[threadIdx.x] - m) / sum;
    }
}

// ---------------- exact global top-k threshold (radix select) ----------------
__global__ void topk_kernel(const int* __restrict__ cap) {
    __shared__ int hist[256];
    __shared__ unsigned sh_prefix;
    __shared__ int sh_k;
    int k = S_TOK * cap[0];
    if (k < 1) k = 1;
    if (k > NSCORES) k = NSCORES;
    unsigned prefix = 0, mask = 0;
    int kk = k;
    for (int shift = 24; shift >= 0; shift -= 8) {
        for (int i = threadIdx.x; i < 256; i += blockDim.x) hist[i] = 0;
        __syncthreads();
        for (int i = threadIdx.x; i < NSCORES; i += blockDim.x) {
            unsigned u = __float_as_uint(g_scores[i]);
            if ((u & mask) == prefix) atomicAdd(&hist[(u >> shift) & 255], 1);
        }
        __syncthreads();
        if (threadIdx.x == 0) {
            int rem = kk, b = 255;
            for (; b >= 0; --b) {
                if (rem <= hist[b]) break;
                rem -= hist[b];
            }
            if (b < 0) b = 0;
            sh_prefix = prefix | ((unsigned)b << shift);
            sh_k = rem;
        }
        __syncthreads();
        prefix = sh_prefix;
        kk = sh_k;
        mask |= (0xFFu << shift);
        __syncthreads();
    }
    if (threadIdx.x == 0) g_thresh = __uint_as_float(prefix);
}

__global__ void build_kernel() {
    int i = blockIdx.x * blockDim.x + threadIdx.x;
    if (i >= NSCORES) return;
    float sc = g_scores[i];
    int e = i >> 12;
    int p = -1;
    if (sc >= g_thresh) {
        int r = atomicAdd(&g_cnt[e], 1);
        g_rows[e * S_TOK + r] = i & (S_TOK - 1);
        g_w[e * S_TOK + r]    = sc;
        p = r;
    }
    g_pos[i] = p;
}

// ---------------- tf32 tensor-core GEMM (pre-cvt smem, paired A loads) ------
#define BM 128
#define BN 128
#define BK 16
#define ASTRW 24      // As row stride in 32-bit words (pair-interleaved k)
#define BSTR 136      // Bs row stride in words

__device__ __forceinline__ unsigned f2tf(float f) {
    unsigned u;
    asm("cvt.rna.tf32.f32 %0, %1;" : "=r"(u) : "f"(f));
    return u;
}
__device__ __forceinline__ void mma_tf32(float* c, const unsigned* a, const unsigned* b) {
    asm volatile("mma.sync.aligned.m16n8k8.row.col.f32.tf32.tf32.f32 "
        "{%0,%1,%2,%3}, {%4,%5,%6,%7}, {%8,%9}, {%0,%1,%2,%3};"
        : "+f"(c[0]), "+f"(c[1]), "+f"(c[2]), "+f"(c[3])
        : "r"(a[0]), "r"(a[1]), "r"(a[2]), "r"(a[3]), "r"(b[0]), "r"(b[1]));
}

// store one 8-k group of A (floats v[0..7] = k..k+7) pair-interleaved + tf32
__device__ __forceinline__ void stage_A_group(unsigned* dst, const float* v) {
    #pragma unroll
    for (int j = 0; j < 4; j++) {
        uint2 p;
        p.x = f2tf(v[j]);       // original k = j
        p.y = f2tf(v[j + 4]);   // original k = j+4
        *(uint2*)(dst + 2 * j) = p;
    }
}

__device__ __forceinline__ void compute_bk16(const unsigned* As, const unsigned* Bs,
                                             int wm, int wn, int gid, int tig,
                                             float acc[4][4][4]) {
    #pragma unroll
    for (int ks = 0; ks < 2; ks++) {
        unsigned af[4][4], bf[4][2];
        #pragma unroll
        for (int mt = 0; mt < 4; mt++) {
            int r = wm + mt * 16 + gid;
            uint2 u02 = *(const uint2*)(As + (size_t)r * ASTRW + ks * 8 + 2 * tig);
            uint2 u13 = *(const uint2*)(As + (size_t)(r + 8) * ASTRW + ks * 8 + 2 * tig);
            af[mt][0] = u02.x;  // (gid,   k=tig)
            af[mt][1] = u13.x;  // (gid+8, k=tig)
            af[mt][2] = u02.y;  // (gid,   k=tig+4)
            af[mt][3] = u13.y;  // (gid+8, k=tig+4)
        }
        #pragma unroll
        for (int nt = 0; nt < 4; nt++) {
            const unsigned* b0 = Bs + (size_t)(ks * 8 + tig) * BSTR + wn + nt * 8 + gid;
            bf[nt][0] = b0[0];
            bf[nt][1] = b0[4 * BSTR];
        }
        #pragma unroll
        for (int mt = 0; mt < 4; mt++)
            #pragma unroll
            for (int nt = 0; nt < 4; nt++)
                mma_tf32(acc[mt][nt], af[mt], bf[nt]);
    }
}

// GEMM1: g_hidden[e][r][h] = gelu( x[tok[r]] @ w1[e] + b1[e] ),  K=DIM
__global__ __launch_bounds__(256, 2)
void gemm1_kernel(const float* __restrict__ x,
                  const float* __restrict__ w1,
                  const float* __restrict__ b1) {
    int e = blockIdx.z;
    int n = g_cnt[e];
    int row0 = blockIdx.y * BM;
    if (row0 >= n) return;
    int col0 = blockIdx.x * BN;
    const float* Bg = w1 + (size_t)e * DIM * HID;
    const int ldb = HID;
    const int K = DIM;

    __shared__ __align__(16) unsigned As[BM * ASTRW];
    __shared__ __align__(16) unsigned Bs[BK * BSTR];
    __shared__ int toks[BM];

    int tid = threadIdx.x;
    if (tid < BM) {
        int mg = row0 + tid;
        if (mg >= n) mg = n - 1;
        toks[tid] = g_rows[e * S_TOK + mg];
    }
    __syncthreads();

    int lane = tid & 31, warp = tid >> 5;
    int gid = lane >> 2, tig = lane & 3;
    int wm = (warp & 1) * 64, wn = (warp >> 1) * 32;

    float acc[4][4][4];
    #pragma unroll
    for (int mt = 0; mt < 4; mt++)
        #pragma unroll
        for (int nt = 0; nt < 4; nt++)
            #pragma unroll
            for (int i = 0; i < 4; i++) acc[mt][nt][i] = 0.f;

    // staging: A thread -> row aR, 8-k group grp; B thread -> 2 float4 rows
    int aR = tid >> 1, grp = tid & 1;
    const float* aSrc = x + (size_t)toks[aR] * DIM + grp * 8;
    unsigned* aDst = As + (size_t)aR * ASTRW + grp * 8;
    int bk0 = tid >> 5, bn0 = lane * 4;   // two rows: bk0, bk0+8
    const float* bSrc0 = Bg + (size_t)bk0 * ldb + col0 + bn0;
    const float* bSrc1 = Bg + (size_t)(bk0 + 8) * ldb + col0 + bn0;
    unsigned* bDst0 = Bs + (size_t)bk0 * BSTR + bn0;
    unsigned* bDst1 = Bs + (size_t)(bk0 + 8) * BSTR + bn0;

    float ra[8];
    float4 rb0, rb1;
    *(float4*)&ra[0] = *(const float4*)aSrc;
    *(float4*)&ra[4] = *(const float4*)(aSrc + 4);
    rb0 = *(const float4*)bSrc0;
    rb1 = *(const float4*)bSrc1;

    for (int k0 = 0;;) {
        stage_A_group(aDst, ra);
        uint4 c0, c1;
        c0.x = f2tf(rb0.x); c0.y = f2tf(rb0.y); c0.z = f2tf(rb0.z); c0.w = f2tf(rb0.w);
        c1.x = f2tf(rb1.x); c1.y = f2tf(rb1.y); c1.z = f2tf(rb1.z); c1.w = f2tf(rb1.w);
        *(uint4*)bDst0 = c0;
        *(uint4*)bDst1 = c1;
        __syncthreads();

        k0 += BK;
        bool more = (k0 < K);
        if (more) {
            *(float4*)&ra[0] = *(const float4*)(aSrc + k0);
            *(float4*)&ra[4] = *(const float4*)(aSrc + k0 + 4);
            rb0 = *(const float4*)(bSrc0 + (size_t)k0 * ldb);
            rb1 = *(const float4*)(bSrc1 + (size_t)k0 * ldb);
        }
        compute_bk16(As, Bs, wm, wn, gid, tig, acc);
        if (!more) break;
        __syncthreads();
    }

    const float* b1e = b1 + (size_t)e * HID;
    float* Hb = g_hidden + (size_t)e * S_TOK * HID;
    #pragma unroll
    for (int mt = 0; mt < 4; mt++) {
        #pragma unroll
        for (int half = 0; half < 2; half++) {
            int r = row0 + wm + mt * 16 + gid + half * 8;
            if (r >= n) continue;
            #pragma unroll
            for (int nt = 0; nt < 4; nt++) {
                int c = col0 + wn + nt * 8 + 2 * tig;
                float v0 = acc[mt][nt][half * 2 + 0] + b1e[c];
                float v1 = acc[mt][nt][half * 2 + 1] + b1e[c + 1];
                float t0 = tanhf(0.7978845608028654f * (v0 + 0.044715f * v0 * v0 * v0));
                float t1 = tanhf(0.7978845608028654f * (v1 + 0.044715f * v1 * v1 * v1));
                float2 o;
                o.x = 0.5f * v0 * (1.0f + t0);
                o.y = 0.5f * v1 * (1.0f + t1);
                *(float2*)&Hb[(size_t)r * HID + c] = o;
            }
        }
    }
}

// GEMM2: g_y[e][r][d] = g_w[r] * ( g_hidden[e][r] @ w2[e] + b2[e] ),  K=HID
__global__ __launch_bounds__(256, 2)
void gemm2_kernel(const float* __restrict__ w2,
                  const float* __restrict__ b2) {
    int e = blockIdx.z;
    int n = g_cnt[e];
    int row0 = blockIdx.y * BM;
    if (row0 >= n) return;
    int col0 = blockIdx.x * BN;
    const float* Ag = g_hidden + (size_t)e * S_TOK * HID;
    const float* Bg = w2 + (size_t)e * HID * DIM;
    const int ldb = DIM;
    const int K = HID;

    __shared__ __align__(16) unsigned As[BM * ASTRW];
    __shared__ __align__(16) unsigned Bs[BK * BSTR];

    int tid = threadIdx.x;
    int lane = tid & 31, warp = tid >> 5;
    int gid = lane >> 2, tig = lane & 3;
    int wm = (warp & 1) * 64, wn = (warp >> 1) * 32;

    float acc[4][4][4];
    #pragma unroll
    for (int mt = 0; mt < 4; mt++)
        #pragma unroll
        for (int nt = 0; nt < 4; nt++)
            #pragma unroll
            for (int i = 0; i < 4; i++) acc[mt][nt][i] = 0.f;

    int aR = tid >> 1, grp = tid & 1;
    int mg = row0 + aR; if (mg >= n) mg = n - 1;
    const float* aSrc = Ag + (size_t)mg * HID + grp * 8;
    unsigned* aDst = As + (size_t)aR * ASTRW + grp * 8;
    int bk0 = tid >> 5, bn0 = lane * 4;
    const float* bSrc0 = Bg + (size_t)bk0 * ldb + col0 + bn0;
    const float* bSrc1 = Bg + (size_t)(bk0 + 8) * ldb + col0 + bn0;
    unsigned* bDst0 = Bs + (size_t)bk0 * BSTR + bn0;
    unsigned* bDst1 = Bs + (size_t)(bk0 + 8) * BSTR + bn0;

    float ra[8];
    float4 rb0, rb1;
    *(float4*)&ra[0] = *(const float4*)aSrc;
    *(float4*)&ra[4] = *(const float4*)(aSrc + 4);
    rb0 = *(const float4*)bSrc0;
    rb1 = *(const float4*)bSrc1;

    for (int k0 = 0;;) {
        stage_A_group(aDst, ra);
        uint4 c0, c1;
        c0.x = f2tf(rb0.x); c0.y = f2tf(rb0.y); c0.z = f2tf(rb0.z); c0.w = f2tf(rb0.w);
        c1.x = f2tf(rb1.x); c1.y = f2tf(rb1.y); c1.z = f2tf(rb1.z); c1.w = f2tf(rb1.w);
        *(uint4*)bDst0 = c0;
        *(uint4*)bDst1 = c1;
        __syncthreads();

        k0 += BK;
        bool more = (k0 < K);
        if (more) {
            *(float4*)&ra[0] = *(const float4*)(aSrc + k0);
            *(float4*)&ra[4] = *(const float4*)(aSrc + k0 + 4);
            rb0 = *(const float4*)(bSrc0 + (size_t)k0 * ldb);
            rb1 = *(const float4*)(bSrc1 + (size_t)k0 * ldb);
        }
        compute_bk16(As, Bs, wm, wn, gid, tig, acc);
        if (!more) break;
        __syncthreads();
    }

    const float* b2e = b2 + (size_t)e * DIM;
    #pragma unroll
    for (int mt = 0; mt < 4; mt++) {
        #pragma unroll
        for (int half = 0; half < 2; half++) {
            int r = row0 + wm + mt * 16 + gid + half * 8;
            if (r >= n) continue;
            float wg = g_w[e * S_TOK + r];
            #pragma unroll
            for (int nt = 0; nt < 4; nt++) {
                int c = col0 + wn + nt * 8 + 2 * tig;
                float2 o;
                o.x = wg * (acc[mt][nt][half * 2 + 0] + b2e[c]);
                o.y = wg * (acc[mt][nt][half * 2 + 1] + b2e[c + 1]);
                *(float2*)&g_y[((size_t)e * S_TOK + r) * DIM + c] = o;
            }
        }
    }
}

// ---------------- deterministic combine ----------------
__global__ void combine_kernel(float* __restrict__ out) {
    int s = blockIdx.y;
    int d = blockIdx.x * blockDim.x + threadIdx.x;
    float acc = 0.f;
    #pragma unroll
    for (int e = 0; e < NEXP; e++) {
        int p = g_pos[e * S_TOK + s];
        if (p >= 0) acc += g_y[((size_t)(e * S_TOK + p)) * DIM + d];
    }
    out[(size_t)s * DIM + d] = acc;
}

// ---------------- launch ----------------
extern "C" void kernel_launch(void* const* d_in, const int* in_sizes, int n_in,
                              void* d_out, int out_size) {
    const float* x  = (const float*)d_in[0];
    const float* gw = (const float*)d_in[1];
    const float* eb = (const float*)d_in[2];
    const float* w1 = (const float*)d_in[3];
    const float* b1 = (const float*)d_in[4];
    const float* w2 = (const float*)d_in[5];
    const float* b2 = (const float*)d_in[6];
    const int*  cap = (const int*)d_in[7];
    float* out = (float*)d_out;

    zero_cnt_kernel<<<1, 32>>>();
    router_kernel<<<S_TOK, 256>>>(x, gw, eb);
    topk_kernel<<<1, 256>>>(cap);
    build_kernel<<<NSCORES / 256, 256>>>();
    gemm1_kernel<<<dim3(HID / BN, S_TOK / BM, NEXP), 256>>>(x, w1, b1);
    gemm2_kernel<<<dim3(DIM / BN, S_TOK / BM, NEXP), 256>>>(w2, b2);
    combine_kernel<<<dim3(DIM / 256, S_TOK), 256>>>(out);
}

// round 8
// speedup vs baseline: 1.0385x; 1.0382x over previous
#include <cuda_runtime.h>
#include <cuda_bf16.h>
#include <math.h>
#include <stdint.h>

// Problem constants
#define S_TOK 4096
#define DIM   1024
#define NEXP  8
#define HID   4096
#define NSCORES (NEXP * S_TOK)

// ---------------- device scratch ----------------
__device__ float g_scores[NSCORES];
__device__ float g_thresh;
__device__ int   g_cnt[NEXP];
__device__ int   g_rows[NEXP * S_TOK];
__device__ float g_w[NEXP * S_TOK];
__device__ int   g_pos[NSCORES];
__device__ float g_hidden[(size_t)NEXP * S_TOK * HID];
__device__ float g_y[(size_t)NEXP * S_TOK * DIM];

__global__ void zero_cnt_kernel() {
    if (threadIdx.x < NEXP) g_cnt[threadIdx.x] = 0;
}

// ---------------- router (exact fp32) ----------------
__global__ void router_kernel(const float* __restrict__ x,
                              const float* __restrict__ gw,
                              const float* __restrict__ eb) {
    int s = blockIdx.x;
    int warp = threadIdx.x >> 5, lane = threadIdx.x & 31;
    const float* xs = x + (size_t)s * DIM;
    const float* g  = gw + (size_t)warp * DIM;
    float acc = 0.f;
    for (int i = lane; i < DIM; i += 32) acc += xs[i] * g[i];
    #pragma unroll
    for (int o = 16; o; o >>= 1) acc += __shfl_xor_sync(0xFFFFFFFFu, acc, o);
    __shared__ float l[NEXP];
    if (lane == 0) l[warp] = acc + eb[warp];
    __syncthreads();
    if (threadIdx.x < NEXP) {
        float m = l[0];
        #pragma unroll
        for (int e = 1; e < NEXP; e++) m = fmaxf(m, l[e]);
        float sum = 0.f;
        #pragma unroll
        for (int e = 0; e < NEXP; e++) sum += expf(l[e] - m);
        g_scores[threadIdx.x * S_TOK + s] = expf(l[threadIdx.x] - m) / sum;
    }
}

// ---------------- exact global top-k threshold (radix select) ----------------
__global__ void topk_kernel(const int* __restrict__ cap) {
    __shared__ int hist[256];
    __shared__ unsigned sh_prefix;
    __shared__ int sh_k;
    int k = S_TOK * cap[0];
    if (k < 1) k = 1;
    if (k > NSCORES) k = NSCORES;
    unsigned prefix = 0, mask = 0;
    int kk = k;
    for (int shift = 24; shift >= 0; shift -= 8) {
        for (int i = threadIdx.x; i < 256; i += blockDim.x) hist[i] = 0;
        __syncthreads();
        for (int i = threadIdx.x; i < NSCORES; i += blockDim.x) {
            unsigned u = __float_as_uint(g_scores[i]);
            if ((u & mask) == prefix) atomicAdd(&hist[(u >> shift) & 255], 1);
        }
        __syncthreads();
        if (threadIdx.x == 0) {
            int rem = kk, b = 255;
            for (; b >= 0; --b) {
                if (rem <= hist[b]) break;
                rem -= hist[b];
            }
            if (b < 0) b = 0;
            sh_prefix = prefix | ((unsigned)b << shift);
            sh_k = rem;
        }
        __syncthreads();
        prefix = sh_prefix;
        kk = sh_k;
        mask |= (0xFFu << shift);
        __syncthreads();
    }
    if (threadIdx.x == 0) g_thresh = __uint_as_float(prefix);
}

__global__ void build_kernel() {
    int i = blockIdx.x * blockDim.x + threadIdx.x;
    if (i >= NSCORES) return;
    float sc = g_scores[i];
    int e = i >> 12;
    int p = -1;
    if (sc >= g_thresh) {
        int r = atomicAdd(&g_cnt[e], 1);
        g_rows[e * S_TOK + r] = i & (S_TOK - 1);
        g_w[e * S_TOK + r]    = sc;
        p = r;
    }
    g_pos[i] = p;
}

// ---------------- tf32 GEMM: cp.async 4-stage, occ 2, R3 fragment layout ----
#define BM 128
#define BN 128
#define BK 16
#define STAGES 4
#define ASTR 20                               // A row stride (words), conflict-free
#define BSTR 136                              // B row stride (words), conflict-free
#define A_WORDS (BM * ASTR)                   // 2560
#define B_WORDS (BK * BSTR)                   // 2176
#define STAGE_WORDS (A_WORDS + B_WORDS)       // 4736
#define STAGE_BYTES (STAGE_WORDS * 4)         // 18944
#define TOKS_OFF (STAGES * STAGE_BYTES)       // 75776
#define SMEM_TOTAL (TOKS_OFF + BM * 4)        // 76288

#define CP16(dst_s, src_g) \
    asm volatile("cp.async.cg.shared.global [%0], [%1], 16;" :: "r"(dst_s), "l"(src_g) : "memory")
#define CP_COMMIT() asm volatile("cp.async.commit_group;" ::: "memory")
#define CP_WAIT2()  asm volatile("cp.async.wait_group 2;" ::: "memory")

__device__ __forceinline__ unsigned ldcvt(const float* p) {
    unsigned u;
    float f = *p;
    asm("cvt.rna.tf32.f32 %0, %1;" : "=r"(u) : "f"(f));
    return u;
}
__device__ __forceinline__ void mma_tf32(float* c, const unsigned* a, const unsigned* b) {
    asm volatile("mma.sync.aligned.m16n8k8.row.col.f32.tf32.tf32.f32 "
        "{%0,%1,%2,%3}, {%4,%5,%6,%7}, {%8,%9}, {%0,%1,%2,%3};"
        : "+f"(c[0]), "+f"(c[1]), "+f"(c[2]), "+f"(c[3])
        : "r"(a[0]), "r"(a[1]), "r"(a[2]), "r"(a[3]), "r"(b[0]), "r"(b[1]));
}
__device__ __forceinline__ uint32_t smem_u32(const void* p) {
    uint32_t a;
    asm("{ .reg .u64 t; cvta.to.shared.u64 t, %1; cvt.u32.u64 %0, t; }" : "=r"(a) : "l"(p));
    return a;
}

__device__ __forceinline__ void compute_stage(const float* smem_f, int slot,
                                              int wm, int wn, int gid, int tig,
                                              float acc[4][4][4]) {
    const float* As = smem_f + (size_t)slot * STAGE_WORDS;
    const float* Bs = As + A_WORDS;
    #pragma unroll
    for (int ks = 0; ks < 2; ks++) {
        unsigned af[4][4], bf[4][2];
        #pragma unroll
        for (int mt = 0; mt < 4; mt++) {
            const float* a0 = As + (size_t)(wm + mt * 16 + gid) * ASTR + ks * 8 + tig;
            af[mt][0] = ldcvt(a0);
            af[mt][1] = ldcvt(a0 + 8 * ASTR);
            af[mt][2] = ldcvt(a0 + 4);
            af[mt][3] = ldcvt(a0 + 8 * ASTR + 4);
        }
        #pragma unroll
        for (int nt = 0; nt < 4; nt++) {
            const float* b0 = Bs + (size_t)(ks * 8 + tig) * BSTR + wn + nt * 8 + gid;
            bf[nt][0] = ldcvt(b0);
            bf[nt][1] = ldcvt(b0 + 4 * BSTR);
        }
        #pragma unroll
        for (int mt = 0; mt < 4; mt++)
            #pragma unroll
            for (int nt = 0; nt < 4; nt++)
                mma_tf32(acc[mt][nt], af[mt], bf[nt]);
    }
}

// stage copy: A thread t -> row t>>1, 8-float group (t&1); B thread -> row t>>4, 8 cols
#define STAGE_CP(slotu, k0, aSrc, bSrc, ldb, aDstW, bDstW, sbase)                    \
    do {                                                                             \
        uint32_t so_ = (sbase) + (uint32_t)(slotu) * STAGE_BYTES;                    \
        const float* as_ = (aSrc) + (k0);                                            \
        const float* bs_ = (bSrc) + (size_t)(k0) * (ldb);                            \
        CP16(so_ + (aDstW) * 4u, as_);                                               \
        CP16(so_ + ((aDstW) + 4) * 4u, as_ + 4);                                     \
        CP16(so_ + (bDstW) * 4u, bs_);                                               \
        CP16(so_ + ((bDstW) + 4) * 4u, bs_ + 4);                                     \
    } while (0)

// GEMM1: g_hidden[e][r][h] = gelu( x[tok[r]] @ w1[e] + b1[e] ),  K=DIM
__global__ __launch_bounds__(256, 2)
void gemm1_kernel(const float* __restrict__ x,
                  const float* __restrict__ w1,
                  const float* __restrict__ b1) {
    int e = blockIdx.z;
    int n = g_cnt[e];
    int row0 = blockIdx.y * BM;
    if (row0 >= n) return;
    int col0 = blockIdx.x * BN;
    const float* Bg = w1 + (size_t)e * DIM * HID;
    const int ldb = HID;
    const int KIT = DIM / BK;

    extern __shared__ char smem[];
    const float* smem_f = (const float*)smem;
    int* toks = (int*)(smem + TOKS_OFF);
    int tid = threadIdx.x;

    if (tid < BM) {
        int mg = row0 + tid;
        if (mg >= n) mg = n - 1;
        toks[tid] = g_rows[e * S_TOK + mg];
    }
    __syncthreads();

    int lane = tid & 31, warp = tid >> 5;
    int gid = lane >> 2, tig = lane & 3;
    int wm = (warp & 1) * 64, wn = (warp >> 1) * 32;

    // staging addresses
    int aR = tid >> 1, aQ = (tid & 1) * 8;
    const float* aSrc = x + (size_t)toks[aR] * DIM + aQ;
    uint32_t aDstW = (uint32_t)(aR * ASTR + aQ);
    int bR = tid >> 4, bC = (tid & 15) * 8;
    const float* bSrc = Bg + (size_t)bR * ldb + col0 + bC;
    uint32_t bDstW = (uint32_t)(A_WORDS + bR * BSTR + bC);
    uint32_t sbase = smem_u32(smem);

    float acc[4][4][4];
    #pragma unroll
    for (int mt = 0; mt < 4; mt++)
        #pragma unroll
        for (int nt = 0; nt < 4; nt++)
            #pragma unroll
            for (int i = 0; i < 4; i++) acc[mt][nt][i] = 0.f;

    #pragma unroll
    for (int s = 0; s < STAGES - 1; s++) {
        STAGE_CP(s, s * BK, aSrc, bSrc, ldb, aDstW, bDstW, sbase);
        CP_COMMIT();
    }

    for (int it = 0; it < KIT; it++) {
        CP_WAIT2();
        __syncthreads();
        int nxt = it + STAGES - 1;
        if (nxt < KIT)
            STAGE_CP(nxt & (STAGES - 1), nxt * BK, aSrc, bSrc, ldb, aDstW, bDstW, sbase);
        CP_COMMIT();
        compute_stage(smem_f, it & (STAGES - 1), wm, wn, gid, tig, acc);
    }

    const float* b1e = b1 + (size_t)e * HID;
    float* Hb = g_hidden + (size_t)e * S_TOK * HID;
    #pragma unroll
    for (int mt = 0; mt < 4; mt++) {
        #pragma unroll
        for (int half = 0; half < 2; half++) {
            int r = row0 + wm + mt * 16 + gid + half * 8;
            if (r >= n) continue;
            #pragma unroll
            for (int nt = 0; nt < 4; nt++) {
                int c = col0 + wn + nt * 8 + 2 * tig;
                float v0 = acc[mt][nt][half * 2 + 0] + b1e[c];
                float v1 = acc[mt][nt][half * 2 + 1] + b1e[c + 1];
                float t0 = tanhf(0.7978845608028654f * (v0 + 0.044715f * v0 * v0 * v0));
                float t1 = tanhf(0.7978845608028654f * (v1 + 0.044715f * v1 * v1 * v1));
                float2 o;
                o.x = 0.5f * v0 * (1.0f + t0);
                o.y = 0.5f * v1 * (1.0f + t1);
                *(float2*)&Hb[(size_t)r * HID + c] = o;
            }
        }
    }
}

// GEMM2: g_y[e][r][d] = g_w[r] * ( g_hidden[e][r] @ w2[e] + b2[e] ),  K=HID
__global__ __launch_bounds__(256, 2)
void gemm2_kernel(const float* __restrict__ w2,
                  const float* __restrict__ b2) {
    int e = blockIdx.z;
    int n = g_cnt[e];
    int row0 = blockIdx.y * BM;
    if (row0 >= n) return;
    int col0 = blockIdx.x * BN;
    const float* Ag = g_hidden + (size_t)e * S_TOK * HID;
    const float* Bg = w2 + (size_t)e * HID * DIM;
    const int ldb = DIM;
    const int KIT = HID / BK;

    extern __shared__ char smem[];
    const float* smem_f = (const float*)smem;
    int tid = threadIdx.x;
    int lane = tid & 31, warp = tid >> 5;
    int gid = lane >> 2, tig = lane & 3;
    int wm = (warp & 1) * 64, wn = (warp >> 1) * 32;

    int aR = tid >> 1, aQ = (tid & 1) * 8;
    int mg = row0 + aR; if (mg >= n) mg = n - 1;
    const float* aSrc = Ag + (size_t)mg * HID + aQ;
    uint32_t aDstW = (uint32_t)(aR * ASTR + aQ);
    int bR = tid >> 4, bC = (tid & 15) * 8;
    const float* bSrc = Bg + (size_t)bR * ldb + col0 + bC;
    uint32_t bDstW = (uint32_t)(A_WORDS + bR * BSTR + bC);
    uint32_t sbase = smem_u32(smem);

    float acc[4][4][4];
    #pragma unroll
    for (int mt = 0; mt < 4; mt++)
        #pragma unroll
        for (int nt = 0; nt < 4; nt++)
            #pragma unroll
            for (int i = 0; i < 4; i++) acc[mt][nt][i] = 0.f;

    #pragma unroll
    for (int s = 0; s < STAGES - 1; s++) {
        STAGE_CP(s, s * BK, aSrc, bSrc, ldb, aDstW, bDstW, sbase);
        CP_COMMIT();
    }

    for (int it = 0; it < KIT; it++) {
        CP_WAIT2();
        __syncthreads();
        int nxt = it + STAGES - 1;
        if (nxt < KIT)
            STAGE_CP(nxt & (STAGES - 1), nxt * BK, aSrc, bSrc, ldb, aDstW, bDstW, sbase);
        CP_COMMIT();
        compute_stage(smem_f, it & (STAGES - 1), wm, wn, gid, tig, acc);
    }

    const float* b2e = b2 + (size_t)e * DIM;
    #pragma unroll
    for (int mt = 0; mt < 4; mt++) {
        #pragma unroll
        for (int half = 0; half < 2; half++) {
            int r = row0 + wm + mt * 16 + gid + half * 8;
            if (r >= n) continue;
            float wg = g_w[e * S_TOK + r];
            #pragma unroll
            for (int nt = 0; nt < 4; nt++) {
                int c = col0 + wn + nt * 8 + 2 * tig;
                float2 o;
                o.x = wg * (acc[mt][nt][half * 2 + 0] + b2e[c]);
                o.y = wg * (acc[mt][nt][half * 2 + 1] + b2e[c + 1]);
                *(float2*)&g_y[((size_t)e * S_TOK + r) * DIM + c] = o;
            }
        }
    }
}

// ---------------- deterministic combine ----------------
__global__ void combine_kernel(float* __restrict__ out) {
    int s = blockIdx.y;
    int d = blockIdx.x * blockDim.x + threadIdx.x;
    float acc = 0.f;
    #pragma unroll
    for (int e = 0; e < NEXP; e++) {
        int p = g_pos[e * S_TOK + s];
        if (p >= 0) acc += g_y[((size_t)(e * S_TOK + p)) * DIM + d];
    }
    out[(size_t)s * DIM + d] = acc;
}

// ---------------- launch ----------------
extern "C" void kernel_launch(void* const* d_in, const int* in_sizes, int n_in,
                              void* d_out, int out_size) {
    const float* x  = (const float*)d_in[0];
    const float* gw = (const float*)d_in[1];
    const float* eb = (const float*)d_in[2];
    const float* w1 = (const float*)d_in[3];
    const float* b1 = (const float*)d_in[4];
    const float* w2 = (const float*)d_in[5];
    const float* b2 = (const float*)d_in[6];
    const int*  cap = (const int*)d_in[7];
    float* out = (float*)d_out;

    static int attr_done = 0;
    if (!attr_done) {
        cudaFuncSetAttribute(gemm1_kernel, cudaFuncAttributeMaxDynamicSharedMemorySize, SMEM_TOTAL);
        cudaFuncSetAttribute(gemm2_kernel, cudaFuncAttributeMaxDynamicSharedMemorySize, SMEM_TOTAL);
        attr_done = 1;
    }

    zero_cnt_kernel<<<1, 32>>>();
    router_kernel<<<S_TOK, 256>>>(x, gw, eb);
    topk_kernel<<<1, 256>>>(cap);
    build_kernel<<<NSCORES / 256, 256>>>();
    gemm1_kernel<<<dim3(HID / BN, S_TOK / BM, NEXP), 256, SMEM_TOTAL>>>(x, w1, b1);
    gemm2_kernel<<<dim3(DIM / BN, S_TOK / BM, NEXP), 256, SMEM_TOTAL>>>(w2, b2);
    combine_kernel<<<dim3(DIM / 256, S_TOK), 256>>>(out);
}

// round 9
// speedup vs baseline: 1.6338x; 1.5731x over previous
#include <cuda_runtime.h>
#include <cuda_fp16.h>
#include <math.h>
#include <stdint.h>

// Problem constants
#define S_TOK 4096
#define DIM   1024
#define NEXP  8
#define HID   4096
#define NSCORES (NEXP * S_TOK)

// ---------------- device scratch ----------------
__device__ float g_scores[NSCORES];
__device__ float g_thresh;
__device__ int   g_cnt[NEXP];
__device__ int   g_rows[NEXP * S_TOK];
__device__ float g_w[NEXP * S_TOK];
__device__ int   g_pos[NSCORES];
__device__ __half g_hidden[(size_t)NEXP * S_TOK * HID];   // fp16, k-pair packed
__device__ float g_y[(size_t)NEXP * S_TOK * DIM];

__global__ void zero_cnt_kernel() {
    if (threadIdx.x < NEXP) g_cnt[threadIdx.x] = 0;
}

// ---------------- router (exact fp32) ----------------
__global__ void router_kernel(const float* __restrict__ x,
                              const float* __restrict__ gw,
                              const float* __restrict__ eb) {
    int s = blockIdx.x;
    int warp = threadIdx.x >> 5, lane = threadIdx.x & 31;
    const float* xs = x + (size_t)s * DIM;
    const float* g  = gw + (size_t)warp * DIM;
    float acc = 0.f;
    for (int i = lane; i < DIM; i += 32) acc += xs[i] * g[i];
    #pragma unroll
    for (int o = 16; o; o >>= 1) acc += __shfl_xor_sync(0xFFFFFFFFu, acc, o);
    __shared__ float l[NEXP];
    if (lane == 0) l[warp] = acc + eb[warp];
    __syncthreads();
    if (threadIdx.x < NEXP) {
        float m = l[0];
        #pragma unroll
        for (int e = 1; e < NEXP; e++) m = fmaxf(m, l[e]);
        float sum = 0.f;
        #pragma unroll
        for (int e = 0; e < NEXP; e++) sum += expf(l[e] - m);
        g_scores[threadIdx.x * S_TOK + s] = expf(l[threadIdx.x] - m) / sum;
    }
}

// ---------------- exact global top-k threshold (radix select) ----------------
__global__ void topk_kernel(const int* __restrict__ cap) {
    __shared__ int hist[256];
    __shared__ unsigned sh_prefix;
    __shared__ int sh_k;
    int k = S_TOK * cap[0];
    if (k < 1) k = 1;
    if (k > NSCORES) k = NSCORES;
    unsigned prefix = 0, mask = 0;
    int kk = k;
    for (int shift = 24; shift >= 0; shift -= 8) {
        for (int i = threadIdx.x; i < 256; i += blockDim.x) hist[i] = 0;
        __syncthreads();
        for (int i = threadIdx.x; i < NSCORES; i += blockDim.x) {
            unsigned u = __float_as_uint(g_scores[i]);
            if ((u & mask) == prefix) atomicAdd(&hist[(u >> shift) & 255], 1);
        }
        __syncthreads();
        if (threadIdx.x == 0) {
            int rem = kk, b = 255;
            for (; b >= 0; --b) {
                if (rem <= hist[b]) break;
                rem -= hist[b];
            }
            if (b < 0) b = 0;
            sh_prefix = prefix | ((unsigned)b << shift);
            sh_k = rem;
        }
        __syncthreads();
        prefix = sh_prefix;
        kk = sh_k;
        mask |= (0xFFu << shift);
        __syncthreads();
    }
    if (threadIdx.x == 0) g_thresh = __uint_as_float(prefix);
}

__global__ void build_kernel() {
    int i = blockIdx.x * blockDim.x + threadIdx.x;
    if (i >= NSCORES) return;
    float sc = g_scores[i];
    int e = i >> 12;
    int p = -1;
    if (sc >= g_thresh) {
        int r = atomicAdd(&g_cnt[e], 1);
        g_rows[e * S_TOK + r] = i & (S_TOK - 1);
        g_w[e * S_TOK + r]    = sc;
        p = r;
    }
    g_pos[i] = p;
}

// ---------------- fp16 tensor-core GEMM (m16n8k16, reg double-buffer) -------
#define BM 128
#define BN 128
#define BK 16
#define ASTRW 12      // As row stride in b32 words (8 data + 4 pad): frag banks distinct
#define BSTRW 136     // Bs row stride in b32 words: frag banks distinct

__device__ __forceinline__ void mma_f16(float* c, const unsigned* a, const unsigned* b) {
    asm volatile("mma.sync.aligned.m16n8k16.row.col.f32.f16.f16.f32 "
        "{%0,%1,%2,%3}, {%4,%5,%6,%7}, {%8,%9}, {%0,%1,%2,%3};"
        : "+f"(c[0]), "+f"(c[1]), "+f"(c[2]), "+f"(c[3])
        : "r"(a[0]), "r"(a[1]), "r"(a[2]), "r"(a[3]), "r"(b[0]), "r"(b[1]));
}
__device__ __forceinline__ unsigned pack2(float lo, float hi) {
    __half2 h = __floats2half2_rn(lo, hi);
    return *reinterpret_cast<unsigned*>(&h);
}

// one BK=16 slice: 16 MMAs per warp (4x4 of m16n8k16, warp tile 64x32)
__device__ __forceinline__ void compute_bk16(const unsigned* As, const unsigned* Bs,
                                             int wm, int wn, int gid, int tig,
                                             float acc[4][4][4]) {
    unsigned af[4][4], bf[4][2];
    #pragma unroll
    for (int mt = 0; mt < 4; mt++) {
        int r = wm + mt * 16 + gid;
        af[mt][0] = As[r * ASTRW + tig];
        af[mt][1] = As[(r + 8) * ASTRW + tig];
        af[mt][2] = As[r * ASTRW + tig + 4];
        af[mt][3] = As[(r + 8) * ASTRW + tig + 4];
    }
    #pragma unroll
    for (int nt = 0; nt < 4; nt++) {
        int n = wn + nt * 8 + gid;
        bf[nt][0] = Bs[tig * BSTRW + n];
        bf[nt][1] = Bs[(tig + 4) * BSTRW + n];
    }
    #pragma unroll
    for (int mt = 0; mt < 4; mt++)
        #pragma unroll
        for (int nt = 0; nt < 4; nt++)
            mma_f16(acc[mt][nt], af[mt], bf[nt]);
}

// GEMM1: g_hidden[e][r][h] = gelu( x[tok[r]] @ w1[e] + b1[e] ),  K=DIM
__global__ __launch_bounds__(256, 2)
void gemm1_kernel(const float* __restrict__ x,
                  const float* __restrict__ w1,
                  const float* __restrict__ b1) {
    int e = blockIdx.z;
    int n = g_cnt[e];
    int row0 = blockIdx.y * BM;
    if (row0 >= n) return;
    int col0 = blockIdx.x * BN;
    const float* Bg = w1 + (size_t)e * DIM * HID;
    const int ldb = HID;
    const int K = DIM;

    __shared__ __align__(16) unsigned As[BM * ASTRW];
    __shared__ __align__(16) unsigned Bs[BK / 2 * BSTRW];
    __shared__ int toks[BM];

    int tid = threadIdx.x;
    if (tid < BM) {
        int mg = row0 + tid;
        if (mg >= n) mg = n - 1;
        toks[tid] = g_rows[e * S_TOK + mg];
    }
    __syncthreads();

    int lane = tid & 31, warp = tid >> 5;
    int gid = lane >> 2, tig = lane & 3;
    int wm = (warp & 1) * 64, wn = (warp >> 1) * 32;

    float acc[4][4][4];
    #pragma unroll
    for (int mt = 0; mt < 4; mt++)
        #pragma unroll
        for (int nt = 0; nt < 4; nt++)
            #pragma unroll
            for (int i = 0; i < 4; i++) acc[mt][nt][i] = 0.f;

    // A: thread -> row t>>1, halves 8*(t&1).., word group 4*(t&1)
    int aR = tid >> 1, grp = tid & 1;
    const float* aSrc = x + (size_t)toks[aR] * DIM + grp * 8;
    unsigned* aDst = As + aR * ASTRW + grp * 4;
    // B: thread -> k-pair row kp = warp (0..7), cols lane*4
    int kp = warp, bn0 = lane * 4;
    const float* bSrcE = Bg + (size_t)(2 * kp) * ldb + col0 + bn0;
    const float* bSrcO = bSrcE + ldb;
    unsigned* bDst = Bs + kp * BSTRW + bn0;

    float ra[8];
    float4 rbE, rbO;
    *(float4*)&ra[0] = *(const float4*)aSrc;
    *(float4*)&ra[4] = *(const float4*)(aSrc + 4);
    rbE = *(const float4*)bSrcE;
    rbO = *(const float4*)bSrcO;

    for (int k0 = 0;;) {
        uint4 aw;
        aw.x = pack2(ra[0], ra[1]); aw.y = pack2(ra[2], ra[3]);
        aw.z = pack2(ra[4], ra[5]); aw.w = pack2(ra[6], ra[7]);
        *(uint4*)aDst = aw;
        uint4 bw;
        bw.x = pack2(rbE.x, rbO.x); bw.y = pack2(rbE.y, rbO.y);
        bw.z = pack2(rbE.z, rbO.z); bw.w = pack2(rbE.w, rbO.w);
        *(uint4*)bDst = bw;
        __syncthreads();

        k0 += BK;
        bool more = (k0 < K);
        if (more) {
            *(float4*)&ra[0] = *(const float4*)(aSrc + k0);
            *(float4*)&ra[4] = *(const float4*)(aSrc + k0 + 4);
            rbE = *(const float4*)(bSrcE + (size_t)k0 * ldb);
            rbO = *(const float4*)(bSrcO + (size_t)k0 * ldb);
        }
        compute_bk16(As, Bs, wm, wn, gid, tig, acc);
        if (!more) break;
        __syncthreads();
    }

    const float* b1e = b1 + (size_t)e * HID;
    __half* Hb = g_hidden + (size_t)e * S_TOK * HID;
    #pragma unroll
    for (int mt = 0; mt < 4; mt++) {
        #pragma unroll
        for (int half = 0; half < 2; half++) {
            int r = row0 + wm + mt * 16 + gid + half * 8;
            if (r >= n) continue;
            #pragma unroll
            for (int nt = 0; nt < 4; nt++) {
                int c = col0 + wn + nt * 8 + 2 * tig;
                float v0 = acc[mt][nt][half * 2 + 0] + b1e[c];
                float v1 = acc[mt][nt][half * 2 + 1] + b1e[c + 1];
                float t0 = tanhf(0.7978845608028654f * (v0 + 0.044715f * v0 * v0 * v0));
                float t1 = tanhf(0.7978845608028654f * (v1 + 0.044715f * v1 * v1 * v1));
                float g0 = 0.5f * v0 * (1.0f + t0);
                float g1 = 0.5f * v1 * (1.0f + t1);
                *(unsigned*)&Hb[(size_t)r * HID + c] = pack2(g0, g1);
            }
        }
    }
}

// GEMM2: g_y[e][r][d] = g_w[r] * ( g_hidden[e][r] @ w2[e] + b2[e] ),  K=HID
__global__ __launch_bounds__(256, 2)
void gemm2_kernel(const float* __restrict__ w2,
                  const float* __restrict__ b2) {
    int e = blockIdx.z;
    int n = g_cnt[e];
    int row0 = blockIdx.y * BM;
    if (row0 >= n) return;
    int col0 = blockIdx.x * BN;
    const __half* Ag = g_hidden + (size_t)e * S_TOK * HID;
    const float* Bg = w2 + (size_t)e * HID * DIM;
    const int ldb = DIM;
    const int K = HID;

    __shared__ __align__(16) unsigned As[BM * ASTRW];
    __shared__ __align__(16) unsigned Bs[BK / 2 * BSTRW];

    int tid = threadIdx.x;
    int lane = tid & 31, warp = tid >> 5;
    int gid = lane >> 2, tig = lane & 3;
    int wm = (warp & 1) * 64, wn = (warp >> 1) * 32;

    float acc[4][4][4];
    #pragma unroll
    for (int mt = 0; mt < 4; mt++)
        #pragma unroll
        for (int nt = 0; nt < 4; nt++)
            #pragma unroll
            for (int i = 0; i < 4; i++) acc[mt][nt][i] = 0.f;

    int aR = tid >> 1, grp = tid & 1;
    int mg = row0 + aR; if (mg >= n) mg = n - 1;
    const __half* aSrc = Ag + (size_t)mg * HID + grp * 8;   // already fp16 k-pairs
    unsigned* aDst = As + aR * ASTRW + grp * 4;
    int kp = warp, bn0 = lane * 4;
    const float* bSrcE = Bg + (size_t)(2 * kp) * ldb + col0 + bn0;
    const float* bSrcO = bSrcE + ldb;
    unsigned* bDst = Bs + kp * BSTRW + bn0;

    uint4 ra;
    float4 rbE, rbO;
    ra = *(const uint4*)aSrc;
    rbE = *(const float4*)bSrcE;
    rbO = *(const float4*)bSrcO;

    for (int k0 = 0;;) {
        *(uint4*)aDst = ra;
        uint4 bw;
        bw.x = pack2(rbE.x, rbO.x); bw.y = pack2(rbE.y, rbO.y);
        bw.z = pack2(rbE.z, rbO.z); bw.w = pack2(rbE.w, rbO.w);
        *(uint4*)bDst = bw;
        __syncthreads();

        k0 += BK;
        bool more = (k0 < K);
        if (more) {
            ra = *(const uint4*)(aSrc + k0);
            rbE = *(const float4*)(bSrcE + (size_t)k0 * ldb);
            rbO = *(const float4*)(bSrcO + (size_t)k0 * ldb);
        }
        compute_bk16(As, Bs, wm, wn, gid, tig, acc);
        if (!more) break;
        __syncthreads();
    }

    const float* b2e = b2 + (size_t)e * DIM;
    #pragma unroll
    for (int mt = 0; mt < 4; mt++) {
        #pragma unroll
        for (int half = 0; half < 2; half++) {
            int r = row0 + wm + mt * 16 + gid + half * 8;
            if (r >= n) continue;
            float wg = g_w[e * S_TOK + r];
            #pragma unroll
            for (int nt = 0; nt < 4; nt++) {
                int c = col0 + wn + nt * 8 + 2 * tig;
                float2 o;
                o.x = wg * (acc[mt][nt][half * 2 + 0] + b2e[c]);
                o.y = wg * (acc[mt][nt][half * 2 + 1] + b2e[c + 1]);
                *(float2*)&g_y[((size_t)e * S_TOK + r) * DIM + c] = o;
            }
        }
    }
}

// ---------------- deterministic combine ----------------
__global__ void combine_kernel(float* __restrict__ out) {
    int s = blockIdx.y;
    int d = blockIdx.x * blockDim.x + threadIdx.x;
    float acc = 0.f;
    #pragma unroll
    for (int e = 0; e < NEXP; e++) {
        int p = g_pos[e * S_TOK + s];
        if (p >= 0) acc += g_y[((size_t)(e * S_TOK + p)) * DIM + d];
    }
    out[(size_t)s * DIM + d] = acc;
}

// ---------------- launch ----------------
extern "C" void kernel_launch(void* const* d_in, const int* in_sizes, int n_in,
                              void* d_out, int out_size) {
    const float* x  = (const float*)d_in[0];
    const float* gw = (const float*)d_in[1];
    const float* eb = (const float*)d_in[2];
    const float* w1 = (const float*)d_in[3];
    const float* b1 = (const float*)d_in[4];
    const float* w2 = (const float*)d_in[5];
    const float* b2 = (const float*)d_in[6];
    const int*  cap = (const int*)d_in[7];
    float* out = (float*)d_out;

    zero_cnt_kernel<<<1, 32>>>();
    router_kernel<<<S_TOK, 256>>>(x, gw, eb);
    topk_kernel<<<1, 256>>>(cap);
    build_kernel<<<NSCORES / 256, 256>>>();
    gemm1_kernel<<<dim3(HID / BN, S_TOK / BM, NEXP), 256>>>(x, w1, b1);
    gemm2_kernel<<<dim3(DIM / BN, S_TOK / BM, NEXP), 256>>>(w2, b2);
    combine_kernel<<<dim3(DIM / 256, S_TOK), 256>>>(out);
}

// round 10
// speedup vs baseline: 1.7352x; 1.0621x over previous
#include <cuda_runtime.h>
#include <cuda_fp16.h>
#include <math.h>
#include <stdint.h>

// Problem constants
#define S_TOK 4096
#define DIM   1024
#define NEXP  8
#define HID   4096
#define NSCORES (NEXP * S_TOK)

// ---------------- device scratch ----------------
__device__ float g_scores[NSCORES];
__device__ float g_thresh;
__device__ int   g_cnt[NEXP];
__device__ int   g_rows[NEXP * S_TOK];
__device__ float g_w[NEXP * S_TOK];
__device__ int   g_pos[NSCORES];
__device__ __half g_hidden[(size_t)NEXP * S_TOK * HID];   // fp16, k-pair packed
__device__ float g_y[(size_t)NEXP * S_TOK * DIM];

// ---------------- router (exact fp32) ----------------
__global__ void router_kernel(const float* __restrict__ x,
                              const float* __restrict__ gw,
                              const float* __restrict__ eb) {
    int s = blockIdx.x;
    int warp = threadIdx.x >> 5, lane = threadIdx.x & 31;
    const float* xs = x + (size_t)s * DIM;
    const float* g  = gw + (size_t)warp * DIM;
    float acc = 0.f;
    for (int i = lane; i < DIM; i += 32) acc += xs[i] * g[i];
    #pragma unroll
    for (int o = 16; o; o >>= 1) acc += __shfl_xor_sync(0xFFFFFFFFu, acc, o);
    __shared__ float l[NEXP];
    if (lane == 0) l[warp] = acc + eb[warp];
    __syncthreads();
    if (threadIdx.x < NEXP) {
        float m = l[0];
        #pragma unroll
        for (int e = 1; e < NEXP; e++) m = fmaxf(m, l[e]);
        float sum = 0.f;
        #pragma unroll
        for (int e = 0; e < NEXP; e++) sum += expf(l[e] - m);
        g_scores[threadIdx.x * S_TOK + s] = expf(l[threadIdx.x] - m) / sum;
    }
}

// ---------------- exact global top-k threshold (radix select) ----------------
// also zeroes g_cnt (fused; build_kernel depends on both)
__global__ void topk_kernel(const int* __restrict__ cap) {
    __shared__ int hist[256];
    __shared__ unsigned sh_prefix;
    __shared__ int sh_k;
    if (threadIdx.x < NEXP) g_cnt[threadIdx.x] = 0;
    int k = S_TOK * cap[0];
    if (k < 1) k = 1;
    if (k > NSCORES) k = NSCORES;
    unsigned prefix = 0, mask = 0;
    int kk = k;
    for (int shift = 24; shift >= 0; shift -= 8) {
        for (int i = threadIdx.x; i < 256; i += blockDim.x) hist[i] = 0;
        __syncthreads();
        for (int i = threadIdx.x; i < NSCORES; i += blockDim.x) {
            unsigned u = __float_as_uint(g_scores[i]);
            if ((u & mask) == prefix) atomicAdd(&hist[(u >> shift) & 255], 1);
        }
        __syncthreads();
        if (threadIdx.x == 0) {
            int rem = kk, b = 255;
            for (; b >= 0; --b) {
                if (rem <= hist[b]) break;
                rem -= hist[b];
            }
            if (b < 0) b = 0;
            sh_prefix = prefix | ((unsigned)b << shift);
            sh_k = rem;
        }
        __syncthreads();
        prefix = sh_prefix;
        kk = sh_k;
        mask |= (0xFFu << shift);
        __syncthreads();
    }
    if (threadIdx.x == 0) g_thresh = __uint_as_float(prefix);
}

__global__ void build_kernel() {
    int i = blockIdx.x * blockDim.x + threadIdx.x;
    if (i >= NSCORES) return;
    float sc = g_scores[i];
    int e = i >> 12;
    int p = -1;
    if (sc >= g_thresh) {
        int r = atomicAdd(&g_cnt[e], 1);
        g_rows[e * S_TOK + r] = i & (S_TOK - 1);
        g_w[e * S_TOK + r]    = sc;
        p = r;
    }
    g_pos[i] = p;
}

// ---------------- fp16 tensor-core GEMM (m16n8k16, smem double-buffered) ----
#define BM 128
#define BN 128
#define BK 16
#define ASTRW 12      // As row stride in b32 words (8 data + 4 pad)
#define BSTRW 136     // Bs row stride in b32 words
#define A_WORDS (BM * ASTRW)
#define B_WORDS (8 * BSTRW)

__device__ __forceinline__ void mma_f16(float* c, const unsigned* a, const unsigned* b) {
    asm volatile("mma.sync.aligned.m16n8k16.row.col.f32.f16.f16.f32 "
        "{%0,%1,%2,%3}, {%4,%5,%6,%7}, {%8,%9}, {%0,%1,%2,%3};"
        : "+f"(c[0]), "+f"(c[1]), "+f"(c[2]), "+f"(c[3])
        : "r"(a[0]), "r"(a[1]), "r"(a[2]), "r"(a[3]), "r"(b[0]), "r"(b[1]));
}
__device__ __forceinline__ unsigned pack2(float lo, float hi) {
    __half2 h = __floats2half2_rn(lo, hi);
    return *reinterpret_cast<unsigned*>(&h);
}

__device__ __forceinline__ void compute_bk16(const unsigned* As, const unsigned* Bs,
                                             int wm, int wn, int gid, int tig,
                                             float acc[4][4][4]) {
    unsigned af[4][4], bf[4][2];
    #pragma unroll
    for (int mt = 0; mt < 4; mt++) {
        int r = wm + mt * 16 + gid;
        af[mt][0] = As[r * ASTRW + tig];
        af[mt][1] = As[(r + 8) * ASTRW + tig];
        af[mt][2] = As[r * ASTRW + tig + 4];
        af[mt][3] = As[(r + 8) * ASTRW + tig + 4];
    }
    #pragma unroll
    for (int nt = 0; nt < 4; nt++) {
        int n = wn + nt * 8 + gid;
        bf[nt][0] = Bs[tig * BSTRW + n];
        bf[nt][1] = Bs[(tig + 4) * BSTRW + n];
    }
    #pragma unroll
    for (int mt = 0; mt < 4; mt++)
        #pragma unroll
        for (int nt = 0; nt < 4; nt++)
            mma_f16(acc[mt][nt], af[mt], bf[nt]);
}

// GEMM1: g_hidden[e][r][h] = gelu( x[tok[r]] @ w1[e] + b1[e] ),  K=DIM
__global__ __launch_bounds__(256, 2)
void gemm1_kernel(const float* __restrict__ x,
                  const float* __restrict__ w1,
                  const float* __restrict__ b1) {
    int e = blockIdx.z;
    int n = g_cnt[e];
    int row0 = blockIdx.y * BM;
    if (row0 >= n) return;
    int col0 = blockIdx.x * BN;
    const float* Bg = w1 + (size_t)e * DIM * HID;
    const int ldb = HID;
    const int KIT = DIM / BK;

    __shared__ __align__(16) unsigned As[2][A_WORDS];
    __shared__ __align__(16) unsigned Bs[2][B_WORDS];
    __shared__ int toks[BM];

    int tid = threadIdx.x;
    if (tid < BM) {
        int mg = row0 + tid;
        if (mg >= n) mg = n - 1;
        toks[tid] = g_rows[e * S_TOK + mg];
    }
    __syncthreads();

    int lane = tid & 31, warp = tid >> 5;
    int gid = lane >> 2, tig = lane & 3;
    int wm = (warp & 1) * 64, wn = (warp >> 1) * 32;

    float acc[4][4][4];
    #pragma unroll
    for (int mt = 0; mt < 4; mt++)
        #pragma unroll
        for (int nt = 0; nt < 4; nt++)
            #pragma unroll
            for (int i = 0; i < 4; i++) acc[mt][nt][i] = 0.f;

    int aR = tid >> 1, grp = tid & 1;
    const float* aSrc = x + (size_t)toks[aR] * DIM + grp * 8;
    int kp = warp, bn0 = lane * 4;
    const float* bSrcE = Bg + (size_t)(2 * kp) * ldb + col0 + bn0;
    const float* bSrcO = bSrcE + ldb;
    unsigned aOff = aR * ASTRW + grp * 4;
    unsigned bOff = kp * BSTRW + bn0;

    float ra[8];
    float4 rbE, rbO;
    // chunk 0 -> regs -> buf0
    *(float4*)&ra[0] = *(const float4*)aSrc;
    *(float4*)&ra[4] = *(const float4*)(aSrc + 4);
    rbE = *(const float4*)bSrcE;
    rbO = *(const float4*)bSrcO;
    {
        uint4 aw;
        aw.x = pack2(ra[0], ra[1]); aw.y = pack2(ra[2], ra[3]);
        aw.z = pack2(ra[4], ra[5]); aw.w = pack2(ra[6], ra[7]);
        *(uint4*)&As[0][aOff] = aw;
        uint4 bw;
        bw.x = pack2(rbE.x, rbO.x); bw.y = pack2(rbE.y, rbO.y);
        bw.z = pack2(rbE.z, rbO.z); bw.w = pack2(rbE.w, rbO.w);
        *(uint4*)&Bs[0][bOff] = bw;
    }
    __syncthreads();
    // prefetch chunk 1
    *(float4*)&ra[0] = *(const float4*)(aSrc + BK);
    *(float4*)&ra[4] = *(const float4*)(aSrc + BK + 4);
    rbE = *(const float4*)(bSrcE + (size_t)BK * ldb);
    rbO = *(const float4*)(bSrcO + (size_t)BK * ldb);

    for (int it = 0; it < KIT; it++) {
        int cur = it & 1;
        // issue LDG for chunk it+2 AFTER staging regs of it+1 are consumed below;
        // but issue early to cover latency: stage first, then LDG, then compute.
        if (it + 1 < KIT) {
            uint4 aw;
            aw.x = pack2(ra[0], ra[1]); aw.y = pack2(ra[2], ra[3]);
            aw.z = pack2(ra[4], ra[5]); aw.w = pack2(ra[6], ra[7]);
            *(uint4*)&As[cur ^ 1][aOff] = aw;
            uint4 bw;
            bw.x = pack2(rbE.x, rbO.x); bw.y = pack2(rbE.y, rbO.y);
            bw.z = pack2(rbE.z, rbO.z); bw.w = pack2(rbE.w, rbO.w);
            *(uint4*)&Bs[cur ^ 1][bOff] = bw;
        }
        if (it + 2 < KIT) {
            int k0 = (it + 2) * BK;
            *(float4*)&ra[0] = *(const float4*)(aSrc + k0);
            *(float4*)&ra[4] = *(const float4*)(aSrc + k0 + 4);
            rbE = *(const float4*)(bSrcE + (size_t)k0 * ldb);
            rbO = *(const float4*)(bSrcO + (size_t)k0 * ldb);
        }
        compute_bk16(As[cur], Bs[cur], wm, wn, gid, tig, acc);
        __syncthreads();
    }

    const float* b1e = b1 + (size_t)e * HID;
    __half* Hb = g_hidden + (size_t)e * S_TOK * HID;
    #pragma unroll
    for (int mt = 0; mt < 4; mt++) {
        #pragma unroll
        for (int half = 0; half < 2; half++) {
            int r = row0 + wm + mt * 16 + gid + half * 8;
            if (r >= n) continue;
            #pragma unroll
            for (int nt = 0; nt < 4; nt++) {
                int c = col0 + wn + nt * 8 + 2 * tig;
                float v0 = acc[mt][nt][half * 2 + 0] + b1e[c];
                float v1 = acc[mt][nt][half * 2 + 1] + b1e[c + 1];
                float t0 = tanhf(0.7978845608028654f * (v0 + 0.044715f * v0 * v0 * v0));
                float t1 = tanhf(0.7978845608028654f * (v1 + 0.044715f * v1 * v1 * v1));
                float g0 = 0.5f * v0 * (1.0f + t0);
                float g1 = 0.5f * v1 * (1.0f + t1);
                *(unsigned*)&Hb[(size_t)r * HID + c] = pack2(g0, g1);
            }
        }
    }
}

// GEMM2: g_y[e][r][d] = g_w[r] * ( g_hidden[e][r] @ w2[e] + b2[e] ),  K=HID
__global__ __launch_bounds__(256, 2)
void gemm2_kernel(const float* __restrict__ w2,
                  const float* __restrict__ b2) {
    int e = blockIdx.z;
    int n = g_cnt[e];
    int row0 = blockIdx.y * BM;
    if (row0 >= n) return;
    int col0 = blockIdx.x * BN;
    const __half* Ag = g_hidden + (size_t)e * S_TOK * HID;
    const float* Bg = w2 + (size_t)e * HID * DIM;
    const int ldb = DIM;
    const int KIT = HID / BK;

    __shared__ __align__(16) unsigned As[2][A_WORDS];
    __shared__ __align__(16) unsigned Bs[2][B_WORDS];

    int tid = threadIdx.x;
    int lane = tid & 31, warp = tid >> 5;
    int gid = lane >> 2, tig = lane & 3;
    int wm = (warp & 1) * 64, wn = (warp >> 1) * 32;

    float acc[4][4][4];
    #pragma unroll
    for (int mt = 0; mt < 4; mt++)
        #pragma unroll
        for (int nt = 0; nt < 4; nt++)
            #pragma unroll
            for (int i = 0; i < 4; i++) acc[mt][nt][i] = 0.f;

    int aR = tid >> 1, grp = tid & 1;
    int mg = row0 + aR; if (mg >= n) mg = n - 1;
    const __half* aSrc = Ag + (size_t)mg * HID + grp * 8;   // fp16 k-pairs
    int kp = warp, bn0 = lane * 4;
    const float* bSrcE = Bg + (size_t)(2 * kp) * ldb + col0 + bn0;
    const float* bSrcO = bSrcE + ldb;
    unsigned aOff = aR * ASTRW + grp * 4;
    unsigned bOff = kp * BSTRW + bn0;

    uint4 ra;
    float4 rbE, rbO;
    ra = *(const uint4*)aSrc;
    rbE = *(const float4*)bSrcE;
    rbO = *(const float4*)bSrcO;
    {
        *(uint4*)&As[0][aOff] = ra;
        uint4 bw;
        bw.x = pack2(rbE.x, rbO.x); bw.y = pack2(rbE.y, rbO.y);
        bw.z = pack2(rbE.z, rbO.z); bw.w = pack2(rbE.w, rbO.w);
        *(uint4*)&Bs[0][bOff] = bw;
    }
    __syncthreads();
    ra = *(const uint4*)(aSrc + BK);
    rbE = *(const float4*)(bSrcE + (size_t)BK * ldb);
    rbO = *(const float4*)(bSrcO + (size_t)BK * ldb);

    for (int it = 0; it < KIT; it++) {
        int cur = it & 1;
        if (it + 1 < KIT) {
            *(uint4*)&As[cur ^ 1][aOff] = ra;
            uint4 bw;
            bw.x = pack2(rbE.x, rbO.x); bw.y = pack2(rbE.y, rbO.y);
            bw.z = pack2(rbE.z, rbO.z); bw.w = pack2(rbE.w, rbO.w);
            *(uint4*)&Bs[cur ^ 1][bOff] = bw;
        }
        if (it + 2 < KIT) {
            int k0 = (it + 2) * BK;
            ra = *(const uint4*)(aSrc + k0);
            rbE = *(const float4*)(bSrcE + (size_t)k0 * ldb);
            rbO = *(const float4*)(bSrcO + (size_t)k0 * ldb);
        }
        compute_bk16(As[cur], Bs[cur], wm, wn, gid, tig, acc);
        __syncthreads();
    }

    const float* b2e = b2 + (size_t)e * DIM;
    #pragma unroll
    for (int mt = 0; mt < 4; mt++) {
        #pragma unroll
        for (int half = 0; half < 2; half++) {
            int r = row0 + wm + mt * 16 + gid + half * 8;
            if (r >= n) continue;
            float wg = g_w[e * S_TOK + r];
            #pragma unroll
            for (int nt = 0; nt < 4; nt++) {
                int c = col0 + wn + nt * 8 + 2 * tig;
                float2 o;
                o.x = wg * (acc[mt][nt][half * 2 + 0] + b2e[c]);
                o.y = wg * (acc[mt][nt][half * 2 + 1] + b2e[c + 1]);
                *(float2*)&g_y[((size_t)e * S_TOK + r) * DIM + c] = o;
            }
        }
    }
}

// ---------------- deterministic combine (1 block/token, float4) -------------
__global__ void combine_kernel(float* __restrict__ out) {
    int s = blockIdx.x;
    __shared__ int pos[NEXP];
    if (threadIdx.x < NEXP) pos[threadIdx.x] = g_pos[threadIdx.x * S_TOK + s];
    __syncthreads();
    int d = threadIdx.x * 4;
    float4 acc = make_float4(0.f, 0.f, 0.f, 0.f);
    #pragma unroll
    for (int e = 0; e < NEXP; e++) {
        int p = pos[e];
        if (p >= 0) {
            float4 v = *(const float4*)&g_y[((size_t)(e * S_TOK + p)) * DIM + d];
            acc.x += v.x; acc.y += v.y; acc.z += v.z; acc.w += v.w;
        }
    }
    *(float4*)&out[(size_t)s * DIM + d] = acc;
}

// ---------------- launch ----------------
extern "C" void kernel_launch(void* const* d_in, const int* in_sizes, int n_in,
                              void* d_out, int out_size) {
    const float* x  = (const float*)d_in[0];
    const float* gw = (const float*)d_in[1];
    const float* eb = (const float*)d_in[2];
    const float* w1 = (const float*)d_in[3];
    const float* b1 = (const float*)d_in[4];
    const float* w2 = (const float*)d_in[5];
    const float* b2 = (const float*)d_in[6];
    const int*  cap = (const int*)d_in[7];
    float* out = (float*)d_out;

    router_kernel<<<S_TOK, 256>>>(x, gw, eb);
    topk_kernel<<<1, 256>>>(cap);
    build_kernel<<<NSCORES / 256, 256>>>();
    gemm1_kernel<<<dim3(HID / BN, S_TOK / BM, NEXP), 256>>>(x, w1, b1);
    gemm2_kernel<<<dim3(DIM / BN, S_TOK / BM, NEXP), 256>>>(w2, b2);
    combine_kernel<<<S_TOK, 256>>>(out);
}